// round 16
// baseline (speedup 1.0000x reference)
#include <cuda_runtime.h>
#include <cuda_bf16.h>
#include <stdint.h>
#include <math.h>

#define BATCH 64
#define SEQ 256
#define EMBED 512
#define HIDDEN 1024
#define GATES (4*HIDDEN)
#define MTOT (BATCH*SEQ)   // 16384
#define NBLK 128
#define TPB 256

// ---------------- scratch (__device__ globals; no allocs allowed) ----------------
__device__ float g_Xg[(size_t)MTOT * GATES];
__device__ unsigned g_flags[NBLK];

// recurrent h state, bf16 hi/lo split, layout [b][k]
__device__ __nv_bfloat16 g_hhA[BATCH * HIDDEN];
__device__ __nv_bfloat16 g_hlA[BATCH * HIDDEN];
__device__ __nv_bfloat16 g_hhB[BATCH * HIDDEN];
__device__ __nv_bfloat16 g_hlB[BATCH * HIDDEN];

// bf16 hi/lo split operands for the two big GEMMs
__device__ __nv_bfloat16 g_Eh[(size_t)MTOT * EMBED];
__device__ __nv_bfloat16 g_El[(size_t)MTOT * EMBED];
__device__ __nv_bfloat16 g_Wh[(size_t)GATES * EMBED];
__device__ __nv_bfloat16 g_Wl[(size_t)GATES * EMBED];
__device__ __nv_bfloat16 g_Hh[(size_t)MTOT * HIDDEN];  // written by recurrence
__device__ __nv_bfloat16 g_Hl[(size_t)MTOT * HIDDEN];
__device__ __nv_bfloat16 g_Fh[(size_t)HIDDEN * HIDDEN];
__device__ __nv_bfloat16 g_Fl[(size_t)HIDDEN * HIDDEN];

// ---- smem byte layout of persistent recurrence kernel (R14 layout) ----
// sH: 2 buffers x [2 hl][4 q][64 b][72 bf16] = 2 x 73728 B
#define BUFB     73728
#define OFF_RED  147456      // 6144 floats (24KB): k-split partials / A-scratch
#define OFF_X    172032      // 2048 floats: sX[b][32]
#define OFF_G    180224      // 2048 floats: sG[r][64]
#define SMEM_BYTES 188416

// ---- dynamic smem for mma_gemm: 2 bufs x 4 arrays x 128 rows x 40 bf16 ----
#define GPAD 40
#define GEMM_SMEM (2*4*128*GPAD*2)   // 81920 B
#define GB(b,a) ((b)*(4*128*GPAD) + (a)*(128*GPAD))

__device__ __forceinline__ float sigf(float x) { return 1.0f / (1.0f + __expf(-x)); }

__global__ void zero_state_kernel() {
    int i = blockIdx.x * blockDim.x + threadIdx.x;
    if (i < BATCH * HIDDEN / 2) {
        ((unsigned*)g_hhA)[i] = 0u;
        ((unsigned*)g_hlA)[i] = 0u;
    }
    if (i < NBLK) g_flags[i] = 0u;
}

// ---------------- fused bf16 hi/lo split ----------------
__global__ void split2_kernel(const float* __restrict__ s1, __nv_bfloat16* __restrict__ h1,
                              __nv_bfloat16* __restrict__ l1, int n1,
                              const float* __restrict__ s2, __nv_bfloat16* __restrict__ h2,
                              __nv_bfloat16* __restrict__ l2, int n2)
{
    int i = blockIdx.x * blockDim.x + threadIdx.x;
    if (i < n1) {
        float x = s1[i];
        __nv_bfloat16 h = __float2bfloat16(x);
        h1[i] = h;
        l1[i] = __float2bfloat16(x - __bfloat162float(h));
    } else if (i < n1 + n2) {
        int j = i - n1;
        float x = s2[j];
        __nv_bfloat16 h = __float2bfloat16(x);
        h2[j] = h;
        l2[j] = __float2bfloat16(x - __bfloat162float(h));
    }
}

// ---------------- mma / cp.async wrappers (proven) ----------------
__device__ __forceinline__ void ldm4(unsigned* r, const __nv_bfloat16* p) {
    unsigned a = (unsigned)__cvta_generic_to_shared(p);
    asm volatile("ldmatrix.sync.aligned.m8n8.x4.shared.b16 {%0,%1,%2,%3}, [%4];"
                 : "=r"(r[0]), "=r"(r[1]), "=r"(r[2]), "=r"(r[3]) : "r"(a));
}
__device__ __forceinline__ void ldm2(unsigned* r, const __nv_bfloat16* p) {
    unsigned a = (unsigned)__cvta_generic_to_shared(p);
    asm volatile("ldmatrix.sync.aligned.m8n8.x2.shared.b16 {%0,%1}, [%2];"
                 : "=r"(r[0]), "=r"(r[1]) : "r"(a));
}
__device__ __forceinline__ void mma16816(float* d, const unsigned* a, const unsigned* b) {
    asm volatile("mma.sync.aligned.m16n8k16.row.col.f32.bf16.bf16.f32 "
                 "{%0,%1,%2,%3}, {%4,%5,%6,%7}, {%8,%9}, {%0,%1,%2,%3};"
                 : "+f"(d[0]), "+f"(d[1]), "+f"(d[2]), "+f"(d[3])
                 : "r"(a[0]), "r"(a[1]), "r"(a[2]), "r"(a[3]), "r"(b[0]), "r"(b[1]));
}
__device__ __forceinline__ void cpa16(unsigned dst, const void* src) {
    asm volatile("cp.async.cg.shared.global [%0], [%1], 16;" :: "r"(dst), "l"(src) : "memory");
}
#define CP_COMMIT() asm volatile("cp.async.commit_group;" ::: "memory")
#define CP_WAIT1()  asm volatile("cp.async.wait_group 1;" ::: "memory")
#define CP_WAIT0()  asm volatile("cp.async.wait_group 0;" ::: "memory")

// ---------------- tensor-core GEMM with cp.async double buffering ----------------
__global__ __launch_bounds__(256)
void mma_gemm(const __nv_bfloat16* __restrict__ Ah, const __nv_bfloat16* __restrict__ Al,
              const __nv_bfloat16* __restrict__ Bh, const __nv_bfloat16* __restrict__ Bl,
              const float* __restrict__ bias1, const float* __restrict__ bias2,
              float* __restrict__ C, int M, int N, int K)
{
    extern __shared__ __nv_bfloat16 sbuf[];
    const unsigned smem_u32 = (unsigned)__cvta_generic_to_shared(sbuf);

    const int tid = threadIdx.x;
    const int m0 = blockIdx.y * 128;
    const int n0 = blockIdx.x * 128;
    const int wid = tid >> 5;
    const int lane = tid & 31;
    const int wm = wid & 3;
    const int wn = wid >> 2;

    float acc[2][8][4];
#pragma unroll
    for (int mi = 0; mi < 2; mi++)
#pragma unroll
        for (int ni = 0; ni < 8; ni++)
#pragma unroll
            for (int q = 0; q < 4; q++) acc[mi][ni][q] = 0.0f;

    const int lrow = tid >> 1;
    const int lseg = (tid & 1) * 16;
    const int nch = K >> 5;

    // issue chunk kc into buffer bsel
    auto issue = [&](int kc, int bsel) {
        const __nv_bfloat16* srcs[4] = {
            Ah + (size_t)(m0 + lrow) * K + kc + lseg,
            Al + (size_t)(m0 + lrow) * K + kc + lseg,
            Bh + (size_t)(n0 + lrow) * K + kc + lseg,
            Bl + (size_t)(n0 + lrow) * K + kc + lseg };
#pragma unroll
        for (int a = 0; a < 4; a++) {
            unsigned d = smem_u32 + (unsigned)((GB(bsel,a) + lrow*GPAD + lseg) * 2);
            cpa16(d,      srcs[a]);
            cpa16(d + 16, srcs[a] + 8);
        }
    };

    issue(0, 0);
    CP_COMMIT();

    for (int c = 0; c < nch; c++) {
        if (c + 1 < nch) {
            issue((c + 1) << 5, (c + 1) & 1);
            CP_COMMIT();
            CP_WAIT1();
        } else {
            CP_WAIT0();
        }
        __syncthreads();

        const int cur = c & 1;
        const __nv_bfloat16* cAh = sbuf + GB(cur, 0);
        const __nv_bfloat16* cAl = sbuf + GB(cur, 1);
        const __nv_bfloat16* cBh = sbuf + GB(cur, 2);
        const __nv_bfloat16* cBl = sbuf + GB(cur, 3);

#pragma unroll
        for (int ks = 0; ks < 2; ks++) {
            const int kb = ks * 16;
            unsigned afh[2][4], afl[2][4], bfh[8][2], bfl[8][2];
#pragma unroll
            for (int mi = 0; mi < 2; mi++) {
                const int ar = wm*32 + mi*16 + (lane & 15);
                const int ac = kb + (lane >> 4) * 8;
                ldm4(afh[mi], cAh + ar*GPAD + ac);
                ldm4(afl[mi], cAl + ar*GPAD + ac);
            }
#pragma unroll
            for (int ni = 0; ni < 8; ni++) {
                const int br = wn*64 + ni*8 + (lane & 7);
                const int bc = kb + ((lane >> 3) & 1) * 8;
                ldm2(bfh[ni], cBh + br*GPAD + bc);
                ldm2(bfl[ni], cBl + br*GPAD + bc);
            }
#pragma unroll
            for (int mi = 0; mi < 2; mi++)
#pragma unroll
                for (int ni = 0; ni < 8; ni++) {
                    mma16816(acc[mi][ni], afh[mi], bfh[ni]);
                    mma16816(acc[mi][ni], afh[mi], bfl[ni]);
                    mma16816(acc[mi][ni], afl[mi], bfh[ni]);
                }
        }
        __syncthreads();
    }

    const int er = lane >> 2;
    const int ec = (lane & 3) * 2;
#pragma unroll
    for (int mi = 0; mi < 2; mi++) {
#pragma unroll
        for (int ni = 0; ni < 8; ni++) {
            const int r = m0 + wm*32 + mi*16 + er;
            const int c = n0 + wn*64 + ni*8 + ec;
            float b0 = (bias1 ? bias1[c]   : 0.0f) + (bias2 ? bias2[c]   : 0.0f);
            float b1 = (bias1 ? bias1[c+1] : 0.0f) + (bias2 ? bias2[c+1] : 0.0f);
            *(float2*)&C[(size_t)r * N + c] =
                make_float2(acc[mi][ni][0] + b0, acc[mi][ni][1] + b1);
            *(float2*)&C[(size_t)(r+8) * N + c] =
                make_float2(acc[mi][ni][2] + b0, acc[mi][ni][3] + b1);
        }
    }
}

// R14 coalesced h-round issue: each cpa16 instruction covers 4 FULL 128B lines
// (8 lanes x 16B per line); all 8 warps issue all quarters.
__device__ __forceinline__ void issue_round(const __nv_bfloat16* hh, const __nv_bfloat16* hl,
                                            unsigned smem_u32, int nb, int c,
                                            int wid, int lane)
{
    const int j16 = (lane & 7) * 16;
    const int g4  = lane >> 3;                 // 0..3
#pragma unroll
    for (int it = 0; it < 8; it++) {
        const int p = wid*32 + it*4 + g4;      // (q,b) pair id, 0..255
        const int q = p >> 6;
        const int b = p & 63;
        const char* sh = (const char*)hh + b*2048 + q*512 + c*128 + j16;
        const char* sl = (const char*)hl + b*2048 + q*512 + c*128 + j16;
        const unsigned dh = smem_u32 + (unsigned)(nb*BUFB + (q*64 + b)*144 + j16);
        const unsigned dl = smem_u32 + (unsigned)(nb*BUFB + ((4+q)*64 + b)*144 + j16);
        cpa16(dh, sh);
        cpa16(dl, sl);
    }
}

// ---------------- persistent LSTM recurrence (R14 verbatim) ----------------
__global__ __launch_bounds__(TPB, 1)
void lstm_persist(const float* __restrict__ Xg, const float* __restrict__ Whh)
{
    extern __shared__ char smem[];
    float* sRed = (float*)(smem + OFF_RED);
    float* sX   = (float*)(smem + OFF_X);
    float* sG   = (float*)(smem + OFF_G);
    const unsigned smem_u32 = (unsigned)__cvta_generic_to_shared(smem);

    const int tid = threadIdx.x;
    const int lane = tid & 31;
    const int wid = tid >> 5;
    const int wm = wid & 1;
    const int wk = wid >> 1;
    const int j0 = blockIdx.x * 8;

    // ---- preload W_hh A-fragments into registers (hi/lo), via smem scratch ----
    unsigned afh[16][4], afl[16][4];
    {
        __nv_bfloat16* sc_hi = (__nv_bfloat16*)(smem + OFF_RED + wid * 1024);
        __nv_bfloat16* sc_lo = sc_hi + 256;
        const int lr = lane & 15;
        const int c8 = (lane >> 4) * 8;
        const int r = wm * 16 + lr;
        const int grow = (r >> 3) * HIDDEN + j0 + (r & 7);
        const float* wrow = Whh + (size_t)grow * HIDDEN;
#pragma unroll 1
        for (int s = 0; s < 16; s++) {
            const int kb = wk * 256 + s * 16 + c8;
            float4 v0 = *(const float4*)(wrow + kb);
            float4 v1 = *(const float4*)(wrow + kb + 4);
            float vv[8] = {v0.x, v0.y, v0.z, v0.w, v1.x, v1.y, v1.z, v1.w};
#pragma unroll
            for (int i = 0; i < 8; i++) {
                __nv_bfloat16 h = __float2bfloat16(vv[i]);
                sc_hi[lr*16 + c8 + i] = h;
                sc_lo[lr*16 + c8 + i] = __float2bfloat16(vv[i] - __bfloat162float(h));
            }
            __syncwarp();
            ldm4(afh[s], &sc_hi[lr*16 + c8]);
            ldm4(afl[s], &sc_lo[lr*16 + c8]);
            __syncwarp();
        }
    }
    __syncthreads();

    const int be = tid >> 2;      // epilogue: batch
    const int jp = tid & 3;       // epilogue: j-pair

    float c0 = 0.0f, c1 = 0.0f;
    __nv_bfloat162 cph = {}, cpl = {};   // carried Hout of previous step
    size_t cho = 0;

    for (int t = 0; t < SEQ; t++) {
        const __nv_bfloat16* hh = (t & 1) ? g_hhB : g_hhA;
        const __nv_bfloat16* hl = (t & 1) ? g_hlB : g_hlA;
        __nv_bfloat16* hhn = (t & 1) ? g_hhA : g_hhB;
        __nv_bfloat16* hln = (t & 1) ? g_hlA : g_hlB;

        // Xg prefetch (constant input; safe before barrier)
        const float* xsrc = Xg + ((size_t)(be * SEQ + t)) * GATES + jp * HIDDEN + j0;
        float4 xv0 = __ldg((const float4*)xsrc);
        float4 xv1 = __ldg((const float4*)(xsrc + 4));

        // ---- grid barrier: flag array, no atomic serialization ----
        __threadfence();
        __syncthreads();
        if (tid == 0)
            *(volatile unsigned*)&g_flags[blockIdx.x] = (unsigned)(t + 1);
        if (t > 0) {                     // overlap: Hout of t-1 during the wait
            *(__nv_bfloat162*)&g_Hh[cho] = cph;
            *(__nv_bfloat162*)&g_Hl[cho] = cpl;
        }
        if (tid < NBLK) {
            volatile unsigned* f = &g_flags[tid];
            while (*f < (unsigned)(t + 1)) { }
        }
        __syncthreads();

        // stage Xg: sX[b][g*8+jj]
        *(float4*)&sX[be*32 + jp*8]     = xv0;
        *(float4*)&sX[be*32 + jp*8 + 4] = xv1;

        float acc[8][4];
#pragma unroll
        for (int ni = 0; ni < 8; ni++)
#pragma unroll
            for (int q = 0; q < 4; q++) acc[ni][q] = 0.0f;

        // round 0 issue
        issue_round(hh, hl, smem_u32, 0, 0, wid, lane);
        CP_COMMIT();

#pragma unroll
        for (int c = 0; c < 4; c++) {
            if (c < 3) {
                issue_round(hh, hl, smem_u32, (c + 1) & 1, c + 1, wid, lane);
                CP_COMMIT();
                CP_WAIT1();
            } else {
                CP_WAIT0();
            }
            __syncthreads();   // round-c data visible to all warps

            const char* bufb = smem + (c & 1) * BUFB;
#pragma unroll
            for (int s2 = 0; s2 < 4; s2++) {
                const int s = c*4 + s2;
                const int bcol = s2*16 + ((lane >> 3) & 1) * 8;
#pragma unroll
                for (int ni = 0; ni < 8; ni++) {
                    unsigned bh[2], bl[2];
                    const __nv_bfloat16* ph =
                        (const __nv_bfloat16*)(bufb + ((wk)*64 + ni*8 + (lane & 7)) * 144) + bcol;
                    const __nv_bfloat16* pl =
                        (const __nv_bfloat16*)(bufb + ((4+wk)*64 + ni*8 + (lane & 7)) * 144) + bcol;
                    ldm2(bh, ph);
                    ldm2(bl, pl);
                    mma16816(acc[ni], afh[s], bh);
                    mma16816(acc[ni], afh[s], bl);
                    mma16816(acc[ni], afl[s], bh);
                }
            }
            __syncthreads();   // done reading buf (c&1) before re-issue
        }

        // ---- k-split reduction across wk, + Xg, -> sG[r][64] ----
        const int er = lane >> 2;
        const int ec = (lane & 3) * 2;
        if (wk > 0) {
            float* dst = sRed + ((wk-1)*2 + wm) * 1024;
#pragma unroll
            for (int ni = 0; ni < 8; ni++) {
                *(float2*)&dst[er*64     + ni*8 + ec] = make_float2(acc[ni][0], acc[ni][1]);
                *(float2*)&dst[(er+8)*64 + ni*8 + ec] = make_float2(acc[ni][2], acc[ni][3]);
            }
        }
        __syncthreads();
        if (wk == 0) {
#pragma unroll
            for (int ni = 0; ni < 8; ni++) {
#pragma unroll
                for (int hf = 0; hf < 2; hf++) {
                    const int row = wm*16 + er + hf*8;
                    const int col = ni*8 + ec;
                    float sx = acc[ni][hf*2], sy = acc[ni][hf*2+1];
#pragma unroll
                    for (int w = 0; w < 3; w++) {
                        float2 v = *(float2*)&sRed[(w*2 + wm)*1024 + (er + hf*8)*64 + col];
                        sx += v.x; sy += v.y;
                    }
                    const int g = row >> 3, jj = row & 7;
                    sx += sX[col*32 + g*8 + jj];
                    sy += sX[(col+1)*32 + g*8 + jj];
                    *(float2*)&sG[row*64 + col] = make_float2(sx, sy);
                }
            }
        }
        __syncthreads();

        // ---- elementwise LSTM update + bf16 split of h ----
        float hv[2];
#pragma unroll
        for (int q = 0; q < 2; q++) {
            const int jl = jp*2 + q;
            float xi = sG[( 0 + jl)*64 + be];
            float xf = sG[( 8 + jl)*64 + be];
            float xg = sG[(16 + jl)*64 + be];
            float xo = sG[(24 + jl)*64 + be];
            float cold = q ? c1 : c0;
            float cn = sigf(xf) * cold + sigf(xi) * tanhf(xg);
            if (q) c1 = cn; else c0 = cn;
            hv[q] = sigf(xo) * tanhf(cn);
        }
        __nv_bfloat162 ph2, pl2;
        ph2.x = __float2bfloat16(hv[0]);
        ph2.y = __float2bfloat16(hv[1]);
        pl2.x = __float2bfloat16(hv[0] - __bfloat162float(ph2.x));
        pl2.y = __float2bfloat16(hv[1] - __bfloat162float(ph2.y));
        *(__nv_bfloat162*)&hhn[be*HIDDEN + j0 + jp*2] = ph2;
        *(__nv_bfloat162*)&hln[be*HIDDEN + j0 + jp*2] = pl2;
        // carry Hout store to the next barrier window (overlap with poll)
        cph = ph2; cpl = pl2;
        cho = ((size_t)(be*SEQ + t))*HIDDEN + j0 + jp*2;
    }
    // final step's Hout
    *(__nv_bfloat162*)&g_Hh[cho] = cph;
    *(__nv_bfloat162*)&g_Hl[cho] = cpl;
}

extern "C" void kernel_launch(void* const* d_in, const int* in_sizes, int n_in,
                              void* d_out, int out_size)
{
    const float* embedded = (const float*)d_in[0];  // [B,T,E]
    const float* W_ih     = (const float*)d_in[1];  // [4H,E]
    const float* W_hh     = (const float*)d_in[2];  // [4H,H]
    const float* b_ih     = (const float*)d_in[3];  // [4H]
    const float* b_hh     = (const float*)d_in[4];  // [4H]
    const float* W_fc     = (const float*)d_in[5];  // [H,H]
    const float* b_fc     = (const float*)d_in[6];  // [H]
    float* out = (float*)d_out;                     // [B,T,H]

    float* dXg;
    cudaGetSymbolAddress((void**)&dXg, g_Xg);
    __nv_bfloat16 *dEh, *dEl, *dWh, *dWl, *dHh, *dHl, *dFh, *dFl;
    cudaGetSymbolAddress((void**)&dEh, g_Eh);
    cudaGetSymbolAddress((void**)&dEl, g_El);
    cudaGetSymbolAddress((void**)&dWh, g_Wh);
    cudaGetSymbolAddress((void**)&dWl, g_Wl);
    cudaGetSymbolAddress((void**)&dHh, g_Hh);
    cudaGetSymbolAddress((void**)&dHl, g_Hl);
    cudaGetSymbolAddress((void**)&dFh, g_Fh);
    cudaGetSymbolAddress((void**)&dFl, g_Fl);

    cudaFuncSetAttribute(lstm_persist,
                         cudaFuncAttributeMaxDynamicSharedMemorySize, SMEM_BYTES);
    cudaFuncSetAttribute(mma_gemm,
                         cudaFuncAttributeMaxDynamicSharedMemorySize, GEMM_SMEM);

    // #1: zero h0 (bf16) + barrier flags
    zero_state_kernel<<<(BATCH*HIDDEN/2 + 255)/256, 256>>>();

    // #2: fused split of embedded + W_ih
    {
        int n1 = MTOT * EMBED, n2 = GATES * EMBED;
        split2_kernel<<<(n1 + n2 + 255)/256, 256>>>(embedded, dEh, dEl, n1,
                                                    W_ih, dWh, dWl, n2);
    }

    // #3: Xg = embedded @ W_ih^T + b_ih + b_hh
    {
        dim3 grid(GATES/128, MTOT/128);
        mma_gemm<<<grid, 256, GEMM_SMEM>>>(dEh, dEl, dWh, dWl, b_ih, b_hh, dXg,
                                           MTOT, GATES, EMBED);
    }

    // #4 (ncu-profiled): recurrence, single persistent tensor-core kernel
    lstm_persist<<<NBLK, TPB, SMEM_BYTES>>>(dXg, W_hh);

    // #5: split W_fc
    {
        int n4 = HIDDEN * HIDDEN;
        split2_kernel<<<(n4 + 255)/256, 256>>>(W_fc, dFh, dFl, n4,
                                               nullptr, nullptr, nullptr, 0);
    }

    // #6: out = Hout @ W_fc^T + b_fc (Hh/Hl written directly by recurrence)
    {
        dim3 grid(HIDDEN/128, MTOT/128);
        mma_gemm<<<grid, 256, GEMM_SMEM>>>(dHh, dHl, dFh, dFl, b_fc, nullptr, out,
                                           MTOT, HIDDEN, HIDDEN);
    }
}

// round 17
// speedup vs baseline: 1.2773x; 1.2773x over previous
#include <cuda_runtime.h>
#include <cuda_bf16.h>
#include <stdint.h>
#include <math.h>

#define BATCH 64
#define SEQ 256
#define EMBED 512
#define HIDDEN 1024
#define GATES (4*HIDDEN)
#define MTOT (BATCH*SEQ)   // 16384
#define NBLK 128
#define TPB 256

// ---------------- scratch (__device__ globals; no allocs allowed) ----------------
__device__ float g_Xg[(size_t)MTOT * GATES];
// one flag per 128B cache line: no false sharing between flags
__device__ unsigned g_flags[NBLK * 32];

// recurrent h state, bf16 hi/lo split, layout [b][k]
__device__ __nv_bfloat16 g_hhA[BATCH * HIDDEN];
__device__ __nv_bfloat16 g_hlA[BATCH * HIDDEN];
__device__ __nv_bfloat16 g_hhB[BATCH * HIDDEN];
__device__ __nv_bfloat16 g_hlB[BATCH * HIDDEN];

// bf16 hi/lo split operands for the two big GEMMs
__device__ __nv_bfloat16 g_Eh[(size_t)MTOT * EMBED];
__device__ __nv_bfloat16 g_El[(size_t)MTOT * EMBED];
__device__ __nv_bfloat16 g_Wh[(size_t)GATES * EMBED];
__device__ __nv_bfloat16 g_Wl[(size_t)GATES * EMBED];
__device__ __nv_bfloat16 g_Hh[(size_t)MTOT * HIDDEN];  // written by recurrence
__device__ __nv_bfloat16 g_Hl[(size_t)MTOT * HIDDEN];
__device__ __nv_bfloat16 g_Fh[(size_t)HIDDEN * HIDDEN];
__device__ __nv_bfloat16 g_Fl[(size_t)HIDDEN * HIDDEN];

// ---- smem byte layout of persistent recurrence kernel (R14 layout) ----
// sH: 2 buffers x [2 hl][4 q][64 b][72 bf16] = 2 x 73728 B
#define BUFB     73728
#define OFF_RED  147456      // 6144 floats (24KB): k-split partials / A-scratch
#define OFF_X    172032      // 2048 floats: sX[b][32]
#define OFF_G    180224      // 2048 floats: sG[r][64]
#define SMEM_BYTES 188416

__device__ __forceinline__ float sigf(float x) { return 1.0f / (1.0f + __expf(-x)); }

__global__ void zero_state_kernel() {
    int i = blockIdx.x * blockDim.x + threadIdx.x;
    if (i < BATCH * HIDDEN / 2) {
        ((unsigned*)g_hhA)[i] = 0u;
        ((unsigned*)g_hlA)[i] = 0u;
    }
    if (i < NBLK * 32) g_flags[i] = 0u;
}

// ---------------- fused bf16 hi/lo split ----------------
__global__ void split2_kernel(const float* __restrict__ s1, __nv_bfloat16* __restrict__ h1,
                              __nv_bfloat16* __restrict__ l1, int n1,
                              const float* __restrict__ s2, __nv_bfloat16* __restrict__ h2,
                              __nv_bfloat16* __restrict__ l2, int n2)
{
    int i = blockIdx.x * blockDim.x + threadIdx.x;
    if (i < n1) {
        float x = s1[i];
        __nv_bfloat16 h = __float2bfloat16(x);
        h1[i] = h;
        l1[i] = __float2bfloat16(x - __bfloat162float(h));
    } else if (i < n1 + n2) {
        int j = i - n1;
        float x = s2[j];
        __nv_bfloat16 h = __float2bfloat16(x);
        h2[j] = h;
        l2[j] = __float2bfloat16(x - __bfloat162float(h));
    }
}

// ---------------- mma / cp.async wrappers (proven) ----------------
__device__ __forceinline__ void ldm4(unsigned* r, const __nv_bfloat16* p) {
    unsigned a = (unsigned)__cvta_generic_to_shared(p);
    asm volatile("ldmatrix.sync.aligned.m8n8.x4.shared.b16 {%0,%1,%2,%3}, [%4];"
                 : "=r"(r[0]), "=r"(r[1]), "=r"(r[2]), "=r"(r[3]) : "r"(a));
}
__device__ __forceinline__ void ldm2(unsigned* r, const __nv_bfloat16* p) {
    unsigned a = (unsigned)__cvta_generic_to_shared(p);
    asm volatile("ldmatrix.sync.aligned.m8n8.x2.shared.b16 {%0,%1}, [%2];"
                 : "=r"(r[0]), "=r"(r[1]) : "r"(a));
}
__device__ __forceinline__ void mma16816(float* d, const unsigned* a, const unsigned* b) {
    asm volatile("mma.sync.aligned.m16n8k16.row.col.f32.bf16.bf16.f32 "
                 "{%0,%1,%2,%3}, {%4,%5,%6,%7}, {%8,%9}, {%0,%1,%2,%3};"
                 : "+f"(d[0]), "+f"(d[1]), "+f"(d[2]), "+f"(d[3])
                 : "r"(a[0]), "r"(a[1]), "r"(a[2]), "r"(a[3]), "r"(b[0]), "r"(b[1]));
}
__device__ __forceinline__ void cpa16(unsigned dst, const void* src) {
    asm volatile("cp.async.cg.shared.global [%0], [%1], 16;" :: "r"(dst), "l"(src) : "memory");
}
#define CP_COMMIT() asm volatile("cp.async.commit_group;" ::: "memory")
#define CP_WAIT1()  asm volatile("cp.async.wait_group 1;" ::: "memory")
#define CP_WAIT0()  asm volatile("cp.async.wait_group 0;" ::: "memory")

// ---------------- tensor-core GEMM (R11/R14 synchronous version, proven) ----------
#define SPAD 40
__global__ __launch_bounds__(256)
void mma_gemm(const __nv_bfloat16* __restrict__ Ah, const __nv_bfloat16* __restrict__ Al,
              const __nv_bfloat16* __restrict__ Bh, const __nv_bfloat16* __restrict__ Bl,
              const float* __restrict__ bias1, const float* __restrict__ bias2,
              float* __restrict__ C, int M, int N, int K)
{
    __shared__ __nv_bfloat16 sAh[128][SPAD];
    __shared__ __nv_bfloat16 sAl[128][SPAD];
    __shared__ __nv_bfloat16 sBh[128][SPAD];
    __shared__ __nv_bfloat16 sBl[128][SPAD];

    const int tid = threadIdx.x;
    const int m0 = blockIdx.y * 128;
    const int n0 = blockIdx.x * 128;
    const int wid = tid >> 5;
    const int lane = tid & 31;
    const int wm = wid & 3;
    const int wn = wid >> 2;

    float acc[2][8][4];
#pragma unroll
    for (int mi = 0; mi < 2; mi++)
#pragma unroll
        for (int ni = 0; ni < 8; ni++)
#pragma unroll
            for (int q = 0; q < 4; q++) acc[mi][ni][q] = 0.0f;

    const int lrow = tid >> 1;
    const int lseg = (tid & 1) * 16;

    for (int kc = 0; kc < K; kc += 32) {
        const size_t aoff = (size_t)(m0 + lrow) * K + kc + lseg;
        const size_t boff = (size_t)(n0 + lrow) * K + kc + lseg;
        *(uint4*)&sAh[lrow][lseg]   = *(const uint4*)(Ah + aoff);
        *(uint4*)&sAh[lrow][lseg+8] = *(const uint4*)(Ah + aoff + 8);
        *(uint4*)&sAl[lrow][lseg]   = *(const uint4*)(Al + aoff);
        *(uint4*)&sAl[lrow][lseg+8] = *(const uint4*)(Al + aoff + 8);
        *(uint4*)&sBh[lrow][lseg]   = *(const uint4*)(Bh + boff);
        *(uint4*)&sBh[lrow][lseg+8] = *(const uint4*)(Bh + boff + 8);
        *(uint4*)&sBl[lrow][lseg]   = *(const uint4*)(Bl + boff);
        *(uint4*)&sBl[lrow][lseg+8] = *(const uint4*)(Bl + boff + 8);
        __syncthreads();

#pragma unroll
        for (int ks = 0; ks < 2; ks++) {
            const int kb = ks * 16;
            unsigned afh[2][4], afl[2][4], bfh[8][2], bfl[8][2];
#pragma unroll
            for (int mi = 0; mi < 2; mi++) {
                const int ar = wm*32 + mi*16 + (lane & 15);
                const int ac = kb + (lane >> 4) * 8;
                ldm4(afh[mi], &sAh[ar][ac]);
                ldm4(afl[mi], &sAl[ar][ac]);
            }
#pragma unroll
            for (int ni = 0; ni < 8; ni++) {
                const int br = wn*64 + ni*8 + (lane & 7);
                const int bc = kb + ((lane >> 3) & 1) * 8;
                ldm2(bfh[ni], &sBh[br][bc]);
                ldm2(bfl[ni], &sBl[br][bc]);
            }
#pragma unroll
            for (int mi = 0; mi < 2; mi++)
#pragma unroll
                for (int ni = 0; ni < 8; ni++) {
                    mma16816(acc[mi][ni], afh[mi], bfh[ni]);
                    mma16816(acc[mi][ni], afh[mi], bfl[ni]);
                    mma16816(acc[mi][ni], afl[mi], bfh[ni]);
                }
        }
        __syncthreads();
    }

    const int er = lane >> 2;
    const int ec = (lane & 3) * 2;
#pragma unroll
    for (int mi = 0; mi < 2; mi++) {
#pragma unroll
        for (int ni = 0; ni < 8; ni++) {
            const int r = m0 + wm*32 + mi*16 + er;
            const int c = n0 + wn*64 + ni*8 + ec;
            float b0 = (bias1 ? bias1[c]   : 0.0f) + (bias2 ? bias2[c]   : 0.0f);
            float b1 = (bias1 ? bias1[c+1] : 0.0f) + (bias2 ? bias2[c+1] : 0.0f);
            *(float2*)&C[(size_t)r * N + c] =
                make_float2(acc[mi][ni][0] + b0, acc[mi][ni][1] + b1);
            *(float2*)&C[(size_t)(r+8) * N + c] =
                make_float2(acc[mi][ni][2] + b0, acc[mi][ni][3] + b1);
        }
    }
}

// R14 coalesced h-round issue: each cpa16 instruction covers 4 FULL 128B lines
// (8 lanes x 16B per line); all 8 warps issue all quarters.
__device__ __forceinline__ void issue_round(const __nv_bfloat16* hh, const __nv_bfloat16* hl,
                                            unsigned smem_u32, int nb, int c,
                                            int wid, int lane)
{
    const int j16 = (lane & 7) * 16;
    const int g4  = lane >> 3;                 // 0..3
#pragma unroll
    for (int it = 0; it < 8; it++) {
        const int p = wid*32 + it*4 + g4;      // (q,b) pair id, 0..255
        const int q = p >> 6;
        const int b = p & 63;
        const char* sh = (const char*)hh + b*2048 + q*512 + c*128 + j16;
        const char* sl = (const char*)hl + b*2048 + q*512 + c*128 + j16;
        const unsigned dh = smem_u32 + (unsigned)(nb*BUFB + (q*64 + b)*144 + j16);
        const unsigned dl = smem_u32 + (unsigned)(nb*BUFB + ((4+q)*64 + b)*144 + j16);
        cpa16(dh, sh);
        cpa16(dl, sl);
    }
}

// ---------------- persistent LSTM recurrence (R14 + padded flags) ----------------
__global__ __launch_bounds__(TPB, 1)
void lstm_persist(const float* __restrict__ Xg, const float* __restrict__ Whh)
{
    extern __shared__ char smem[];
    float* sRed = (float*)(smem + OFF_RED);
    float* sX   = (float*)(smem + OFF_X);
    float* sG   = (float*)(smem + OFF_G);
    const unsigned smem_u32 = (unsigned)__cvta_generic_to_shared(smem);

    const int tid = threadIdx.x;
    const int lane = tid & 31;
    const int wid = tid >> 5;
    const int wm = wid & 1;
    const int wk = wid >> 1;
    const int j0 = blockIdx.x * 8;

    // ---- preload W_hh A-fragments into registers (hi/lo), via smem scratch ----
    unsigned afh[16][4], afl[16][4];
    {
        __nv_bfloat16* sc_hi = (__nv_bfloat16*)(smem + OFF_RED + wid * 1024);
        __nv_bfloat16* sc_lo = sc_hi + 256;
        const int lr = lane & 15;
        const int c8 = (lane >> 4) * 8;
        const int r = wm * 16 + lr;
        const int grow = (r >> 3) * HIDDEN + j0 + (r & 7);
        const float* wrow = Whh + (size_t)grow * HIDDEN;
#pragma unroll 1
        for (int s = 0; s < 16; s++) {
            const int kb = wk * 256 + s * 16 + c8;
            float4 v0 = *(const float4*)(wrow + kb);
            float4 v1 = *(const float4*)(wrow + kb + 4);
            float vv[8] = {v0.x, v0.y, v0.z, v0.w, v1.x, v1.y, v1.z, v1.w};
#pragma unroll
            for (int i = 0; i < 8; i++) {
                __nv_bfloat16 h = __float2bfloat16(vv[i]);
                sc_hi[lr*16 + c8 + i] = h;
                sc_lo[lr*16 + c8 + i] = __float2bfloat16(vv[i] - __bfloat162float(h));
            }
            __syncwarp();
            ldm4(afh[s], &sc_hi[lr*16 + c8]);
            ldm4(afl[s], &sc_lo[lr*16 + c8]);
            __syncwarp();
        }
    }
    __syncthreads();

    const int be = tid >> 2;      // epilogue: batch
    const int jp = tid & 3;       // epilogue: j-pair

    float c0 = 0.0f, c1 = 0.0f;
    __nv_bfloat162 cph = {}, cpl = {};   // carried Hout of previous step
    size_t cho = 0;

    for (int t = 0; t < SEQ; t++) {
        const __nv_bfloat16* hh = (t & 1) ? g_hhB : g_hhA;
        const __nv_bfloat16* hl = (t & 1) ? g_hlB : g_hlA;
        __nv_bfloat16* hhn = (t & 1) ? g_hhA : g_hhB;
        __nv_bfloat16* hln = (t & 1) ? g_hlA : g_hlB;

        // Xg prefetch (constant input; safe before barrier)
        const float* xsrc = Xg + ((size_t)(be * SEQ + t)) * GATES + jp * HIDDEN + j0;
        float4 xv0 = __ldg((const float4*)xsrc);
        float4 xv1 = __ldg((const float4*)(xsrc + 4));

        // ---- grid barrier: line-padded flag array ----
        __threadfence();
        __syncthreads();
        if (tid == 0)
            *(volatile unsigned*)&g_flags[blockIdx.x * 32] = (unsigned)(t + 1);
        if (t > 0) {                     // overlap: Hout of t-1 during the wait
            *(__nv_bfloat162*)&g_Hh[cho] = cph;
            *(__nv_bfloat162*)&g_Hl[cho] = cpl;
        }
        if (tid < NBLK) {
            volatile unsigned* f = &g_flags[tid * 32];
            while (*f < (unsigned)(t + 1)) { }
        }
        __syncthreads();

        // stage Xg: sX[b][g*8+jj]
        *(float4*)&sX[be*32 + jp*8]     = xv0;
        *(float4*)&sX[be*32 + jp*8 + 4] = xv1;

        float acc[8][4];
#pragma unroll
        for (int ni = 0; ni < 8; ni++)
#pragma unroll
            for (int q = 0; q < 4; q++) acc[ni][q] = 0.0f;

        // round 0 issue
        issue_round(hh, hl, smem_u32, 0, 0, wid, lane);
        CP_COMMIT();

#pragma unroll
        for (int c = 0; c < 4; c++) {
            if (c < 3) {
                issue_round(hh, hl, smem_u32, (c + 1) & 1, c + 1, wid, lane);
                CP_COMMIT();
                CP_WAIT1();
            } else {
                CP_WAIT0();
            }
            __syncthreads();   // round-c data visible to all warps

            const char* bufb = smem + (c & 1) * BUFB;
#pragma unroll
            for (int s2 = 0; s2 < 4; s2++) {
                const int s = c*4 + s2;
                const int bcol = s2*16 + ((lane >> 3) & 1) * 8;
#pragma unroll
                for (int ni = 0; ni < 8; ni++) {
                    unsigned bh[2], bl[2];
                    const __nv_bfloat16* ph =
                        (const __nv_bfloat16*)(bufb + ((wk)*64 + ni*8 + (lane & 7)) * 144) + bcol;
                    const __nv_bfloat16* pl =
                        (const __nv_bfloat16*)(bufb + ((4+wk)*64 + ni*8 + (lane & 7)) * 144) + bcol;
                    ldm2(bh, ph);
                    ldm2(bl, pl);
                    mma16816(acc[ni], afh[s], bh);
                    mma16816(acc[ni], afh[s], bl);
                    mma16816(acc[ni], afl[s], bh);
                }
            }
            __syncthreads();   // done reading buf (c&1) before re-issue
        }

        // ---- k-split reduction across wk, + Xg, -> sG[r][64] ----
        const int er = lane >> 2;
        const int ec = (lane & 3) * 2;
        if (wk > 0) {
            float* dst = sRed + ((wk-1)*2 + wm) * 1024;
#pragma unroll
            for (int ni = 0; ni < 8; ni++) {
                *(float2*)&dst[er*64     + ni*8 + ec] = make_float2(acc[ni][0], acc[ni][1]);
                *(float2*)&dst[(er+8)*64 + ni*8 + ec] = make_float2(acc[ni][2], acc[ni][3]);
            }
        }
        __syncthreads();
        if (wk == 0) {
#pragma unroll
            for (int ni = 0; ni < 8; ni++) {
#pragma unroll
                for (int hf = 0; hf < 2; hf++) {
                    const int row = wm*16 + er + hf*8;
                    const int col = ni*8 + ec;
                    float sx = acc[ni][hf*2], sy = acc[ni][hf*2+1];
#pragma unroll
                    for (int w = 0; w < 3; w++) {
                        float2 v = *(float2*)&sRed[(w*2 + wm)*1024 + (er + hf*8)*64 + col];
                        sx += v.x; sy += v.y;
                    }
                    const int g = row >> 3, jj = row & 7;
                    sx += sX[col*32 + g*8 + jj];
                    sy += sX[(col+1)*32 + g*8 + jj];
                    *(float2*)&sG[row*64 + col] = make_float2(sx, sy);
                }
            }
        }
        __syncthreads();

        // ---- elementwise LSTM update + bf16 split of h ----
        float hv[2];
#pragma unroll
        for (int q = 0; q < 2; q++) {
            const int jl = jp*2 + q;
            float xi = sG[( 0 + jl)*64 + be];
            float xf = sG[( 8 + jl)*64 + be];
            float xg = sG[(16 + jl)*64 + be];
            float xo = sG[(24 + jl)*64 + be];
            float cold = q ? c1 : c0;
            float cn = sigf(xf) * cold + sigf(xi) * tanhf(xg);
            if (q) c1 = cn; else c0 = cn;
            hv[q] = sigf(xo) * tanhf(cn);
        }
        __nv_bfloat162 ph2, pl2;
        ph2.x = __float2bfloat16(hv[0]);
        ph2.y = __float2bfloat16(hv[1]);
        pl2.x = __float2bfloat16(hv[0] - __bfloat162float(ph2.x));
        pl2.y = __float2bfloat16(hv[1] - __bfloat162float(ph2.y));
        *(__nv_bfloat162*)&hhn[be*HIDDEN + j0 + jp*2] = ph2;
        *(__nv_bfloat162*)&hln[be*HIDDEN + j0 + jp*2] = pl2;
        // carry Hout store to the next barrier window (overlap with poll)
        cph = ph2; cpl = pl2;
        cho = ((size_t)(be*SEQ + t))*HIDDEN + j0 + jp*2;
    }
    // final step's Hout
    *(__nv_bfloat162*)&g_Hh[cho] = cph;
    *(__nv_bfloat162*)&g_Hl[cho] = cpl;
}

extern "C" void kernel_launch(void* const* d_in, const int* in_sizes, int n_in,
                              void* d_out, int out_size)
{
    const float* embedded = (const float*)d_in[0];  // [B,T,E]
    const float* W_ih     = (const float*)d_in[1];  // [4H,E]
    const float* W_hh     = (const float*)d_in[2];  // [4H,H]
    const float* b_ih     = (const float*)d_in[3];  // [4H]
    const float* b_hh     = (const float*)d_in[4];  // [4H]
    const float* W_fc     = (const float*)d_in[5];  // [H,H]
    const float* b_fc     = (const float*)d_in[6];  // [H]
    float* out = (float*)d_out;                     // [B,T,H]

    float* dXg;
    cudaGetSymbolAddress((void**)&dXg, g_Xg);
    __nv_bfloat16 *dEh, *dEl, *dWh, *dWl, *dHh, *dHl, *dFh, *dFl;
    cudaGetSymbolAddress((void**)&dEh, g_Eh);
    cudaGetSymbolAddress((void**)&dEl, g_El);
    cudaGetSymbolAddress((void**)&dWh, g_Wh);
    cudaGetSymbolAddress((void**)&dWl, g_Wl);
    cudaGetSymbolAddress((void**)&dHh, g_Hh);
    cudaGetSymbolAddress((void**)&dHl, g_Hl);
    cudaGetSymbolAddress((void**)&dFh, g_Fh);
    cudaGetSymbolAddress((void**)&dFl, g_Fl);

    cudaFuncSetAttribute(lstm_persist,
                         cudaFuncAttributeMaxDynamicSharedMemorySize, SMEM_BYTES);

    // #1: zero h0 (bf16) + barrier flags
    zero_state_kernel<<<(BATCH*HIDDEN/2 + 255)/256, 256>>>();

    // #2: fused split of embedded + W_ih
    {
        int n1 = MTOT * EMBED, n2 = GATES * EMBED;
        split2_kernel<<<(n1 + n2 + 255)/256, 256>>>(embedded, dEh, dEl, n1,
                                                    W_ih, dWh, dWl, n2);
    }

    // #3: Xg = embedded @ W_ih^T + b_ih + b_hh
    {
        dim3 grid(GATES/128, MTOT/128);
        mma_gemm<<<grid, 256>>>(dEh, dEl, dWh, dWl, b_ih, b_hh, dXg,
                                MTOT, GATES, EMBED);
    }

    // #4 (ncu-profiled): recurrence, single persistent tensor-core kernel
    lstm_persist<<<NBLK, TPB, SMEM_BYTES>>>(dXg, W_hh);

    // #5: split W_fc
    {
        int n4 = HIDDEN * HIDDEN;
        split2_kernel<<<(n4 + 255)/256, 256>>>(W_fc, dFh, dFl, n4,
                                               nullptr, nullptr, nullptr, 0);
    }

    // #6: out = Hout @ W_fc^T + b_fc (Hh/Hl written directly by recurrence)
    {
        dim3 grid(HIDDEN/128, MTOT/128);
        mma_gemm<<<grid, 256>>>(dHh, dHl, dFh, dFl, b_fc, nullptr, out,
                                MTOT, HIDDEN, HIDDEN);
    }
}